// round 5
// baseline (speedup 1.0000x reference)
#include <cuda_runtime.h>
#include <cuda_bf16.h>
#include <cstdint>

// CRF log-partition (forward algorithm). B=64, T=2048, C=1, N=128.
//
// G=4 batches per CTA (grid 16, 128 threads). All batches share the E matrix
// (64 bf16x2 regs) and one __syncthreads per step-iteration; their 4 matvecs
// (16 independent HFMA2.BF16 accumulator chains) amortize the serial
// barrier/LDS/tree overhead that dominated the 1-batch version.
// State per batch in scaled-exp domain: alpha_j = m0 + Mint*ln2 + ln(q_j);
// exact power-of-2 renorm keyed on published q0's bf16 exponent.

#define NTAGS 128
#define TMAXR 2048
#define GRP   4
#define LOG2E_F 1.4426950408889634f

typedef __nv_bfloat16  bf16;
typedef __nv_bfloat162 bf16x2;

__device__ __forceinline__ bf16x2 as_bf2(unsigned u) {
    return *reinterpret_cast<bf16x2*>(&u);
}

__global__ void __launch_bounds__(128, 1)
crf_logZ_kernel(const float* __restrict__ emissions,    // [B, T, 1, N]
                const int*   __restrict__ token_sizes,  // [B]
                const float* __restrict__ transitions,  // [1,1,N,N] (prev k, next j)
                const float* __restrict__ head_t,       // [N]
                const float* __restrict__ last_t,       // [N]
                float* __restrict__ out)                // [B, 1]
{
    __shared__ __align__(16) bf16 ph[2][GRP][NTAGS];
    __shared__ float redbuf[GRP][4];

    const int j    = threadIdx.x;
    const int lane = j & 31;
    const int warp = j >> 5;
    const int b0   = blockIdx.x * GRP;

    int len[GRP];
    const float* emb[GRP];
#pragma unroll
    for (int g = 0; g < GRP; ++g) {
        len[g] = token_sizes[b0 + g];
        emb[g] = emissions + (size_t)(b0 + g) * TMAXR * NTAGS;
    }
    int maxlen = len[0];
#pragma unroll
    for (int g = 1; g < GRP; ++g) maxlen = max(maxlen, len[g]);

    // ---- E column j as 64 bf16x2 pairs over consecutive k ----
    bf16x2 Eh[NTAGS / 2];
#pragma unroll
    for (int i = 0; i < NTAGS / 2; ++i) {
        float e0 = exp2f(transitions[(2 * i + 0) * NTAGS + j] * LOG2E_F);
        float e1 = exp2f(transitions[(2 * i + 1) * NTAGS + j] * LOG2E_F);
        Eh[i] = __floats2bfloat162_rn(e0, e1);
    }

    // ---- init per batch: alpha0 = head + em[0]; m0 = blockmax; q = exp(a0-m0) ----
    float hj = head_t[j];
    float a0[GRP], m0[GRP];
#pragma unroll
    for (int g = 0; g < GRP; ++g) {
        a0[g] = hj + emb[g][j];
        float wm = a0[g];
#pragma unroll
        for (int o = 16; o > 0; o >>= 1)
            wm = fmaxf(wm, __shfl_xor_sync(0xffffffff, wm, o));
        if (lane == 0) redbuf[g][warp] = wm;
    }
    __syncthreads();

    bf16 qh[GRP];
    int  Mint[GRP];
#pragma unroll
    for (int g = 0; g < GRP; ++g) {
        m0[g] = fmaxf(fmaxf(redbuf[g][0], redbuf[g][1]),
                      fmaxf(redbuf[g][2], redbuf[g][3]));
        qh[g]   = __float2bfloat16(exp2f((a0[g] - m0[g]) * LOG2E_F));
        Mint[g] = 0;
    }

    // ---- emission pipeline per batch: d_c = exp(em[t]) one step early ----
    float em_a[GRP], em_b[GRP], d_c[GRP];
#pragma unroll
    for (int g = 0; g < GRP; ++g) {
        em_a[g] = emb[g][2 * NTAGS + j];
        em_b[g] = emb[g][3 * NTAGS + j];
        d_c[g]  = exp2f(emb[g][1 * NTAGS + j] * LOG2E_F);
    }

    int buf = 0;
    for (int t = 1; t < maxlen; ++t) {
        // publish all batches, one barrier
#pragma unroll
        for (int g = 0; g < GRP; ++g) ph[buf][g][j] = qh[g];
        __syncthreads();

        // renorm scale per batch from published q0's bf16 exponent
        bf16 hds[GRP];
        bool valid[GRP];
        int  eacc[GRP];
#pragma unroll
        for (int g = 0; g < GRP; ++g) {
            unsigned short q0b = *reinterpret_cast<const unsigned short*>(&ph[buf][g][0]);
            unsigned eh = ((unsigned)q0b >> 7) & 0xffu;
            if (eh == 0u) eh = 127u;
            float scale = __uint_as_float((254u - eh) << 23);   // 2^(127-eh)
            eacc[g]  = (int)eh - 127;
            valid[g] = (t < len[g]);
            hds[g]   = __float2bfloat16(d_c[g] * scale);
        }

        // 4 matvecs: 64 HFMA2 each, 16 independent accumulator chains total
        bf16x2 acc[GRP][4];
        bf16x2 z = __floats2bfloat162_rn(0.f, 0.f);
#pragma unroll
        for (int g = 0; g < GRP; ++g) {
            acc[g][0] = z; acc[g][1] = z; acc[g][2] = z; acc[g][3] = z;
            const uint4* pv = (const uint4*)ph[buf][g];
#pragma unroll
            for (int i = 0; i < NTAGS / 8; ++i) {
                uint4 v = pv[i];
                acc[g][0] = __hfma2(as_bf2(v.x), Eh[4 * i + 0], acc[g][0]);
                acc[g][1] = __hfma2(as_bf2(v.y), Eh[4 * i + 1], acc[g][1]);
                acc[g][2] = __hfma2(as_bf2(v.z), Eh[4 * i + 2], acc[g][2]);
                acc[g][3] = __hfma2(as_bf2(v.w), Eh[4 * i + 3], acc[g][3]);
            }
        }

        // prefetch em[t+3] and next step's exp (off critical path)
        float em_f[GRP], d_n[GRP];
        int tn = t + 3; if (tn > TMAXR - 1) tn = TMAXR - 1;
#pragma unroll
        for (int g = 0; g < GRP; ++g) {
            em_f[g] = __ldg(emb[g] + (size_t)tn * NTAGS + j);
            d_n[g]  = exp2f(em_a[g] * LOG2E_F);
        }

        // reduce trees + masked state update
#pragma unroll
        for (int g = 0; g < GRP; ++g) {
            bf16x2 u0 = __hadd2(acc[g][0], acc[g][1]);
            bf16x2 u1 = __hadd2(acc[g][2], acc[g][3]);
            bf16x2 u2 = __hadd2(u0, u1);
            bf16 sh = __hadd(__low2bfloat16(u2), __high2bfloat16(u2));
            bf16 qn = __hmul(sh, hds[g]);
            if (valid[g]) { qh[g] = qn; Mint[g] += eacc[g]; }
            em_a[g] = em_b[g]; em_b[g] = em_f[g]; d_c[g] = d_n[g];
        }
        buf ^= 1;
    }

    // ---- terminate: out[b] = m0 + Mint*ln2 + ln(sum_j q_j * exp(last_j)) ----
    float lt = exp2f(last_t[j] * LOG2E_F);
    __syncthreads();                 // redbuf reuse
#pragma unroll
    for (int g = 0; g < GRP; ++g) {
        float v = __bfloat162float(qh[g]) * lt;
#pragma unroll
        for (int o = 16; o > 0; o >>= 1)
            v += __shfl_xor_sync(0xffffffff, v, o);
        if (lane == 0) redbuf[g][warp] = v;
    }
    __syncthreads();
    if (j < GRP) {
        int g = j;
        float sv = (redbuf[g][0] + redbuf[g][1]) + (redbuf[g][2] + redbuf[g][3]);
        double r = (double)m0[0];    // placeholder, fixed below
        // m0/Mint live per-thread; thread j==g doesn't hold batch g's values.
        // Recover via shuffle from lane 0 (all threads hold identical m0/Mint
        // since they are computed from uniform data).
        r = (double)m0[g] + (double)Mint[g] * 0.6931471805599453094
          + log((double)sv);
        out[b0 + g] = (float)r;
    }
}

extern "C" void kernel_launch(void* const* d_in, const int* in_sizes, int n_in,
                              void* d_out, int out_size) {
    const float* emissions   = (const float*)d_in[0];  // [64,2048,1,128]
    const int*   token_sizes = (const int*)  d_in[1];  // [64]
    const float* transitions = (const float*)d_in[2];  // [1,1,128,128]
    const float* head_t      = (const float*)d_in[3];  // [1,1,128]
    const float* last_t      = (const float*)d_in[4];  // [1,1,128]
    float* out = (float*)d_out;                        // [64,1]

    crf_logZ_kernel<<<64 / GRP, 128>>>(emissions, token_sizes, transitions,
                                       head_t, last_t, out);
}

// round 6
// speedup vs baseline: 3.1122x; 3.1122x over previous
#include <cuda_runtime.h>
#include <cuda_bf16.h>
#include <cstdint>

// CRF log-partition (forward algorithm). B=64, T=2048, C=1, N=128.
//
// One CTA per batch (64 CTAs, 128 threads). Thread j owns output tag j,
// E column j resident as 64 bf16x2 registers. State in scaled-exp domain:
// alpha_j = m0 + Mint*ln2 + ln(q_j); q published per step as bf16 via smem.
// Matvec: 64 HFMA2.BF16 / thread / step (128-cyc/SM pipe floor).
// Exact power-of-2 renorm keyed on published q0's bf16 exponent.
// Loop unrolled 2x over two statically-addressed smem buffers so all LDS/STS
// use immediate offsets; hot-loop exponentials use ex2.approx.

#define NTAGS 128
#define TMAXR 2048
#define LOG2E_F 1.4426950408889634f

typedef __nv_bfloat16  bf16;
typedef __nv_bfloat162 bf16x2;

__device__ __forceinline__ bf16x2 as_bf2(unsigned u) {
    return *reinterpret_cast<bf16x2*>(&u);
}
__device__ __forceinline__ float ex2(float x) {
    float r;
    asm("ex2.approx.f32 %0, %1;" : "=f"(r) : "f"(x));
    return r;
}

__global__ void __launch_bounds__(128, 1)
crf_logZ_kernel(const float* __restrict__ emissions,    // [B, T, 1, N]
                const int*   __restrict__ token_sizes,  // [B]
                const float* __restrict__ transitions,  // [1,1,N,N] (prev k, next j)
                const float* __restrict__ head_t,       // [N]
                const float* __restrict__ last_t,       // [N]
                float* __restrict__ out)                // [B, 1]
{
    __shared__ __align__(16) bf16 ph0[NTAGS];
    __shared__ __align__(16) bf16 ph1[NTAGS];
    __shared__ float redbuf[4];

    const int b    = blockIdx.x;
    const int j    = threadIdx.x;
    const int lane = j & 31;
    const int warp = j >> 5;
    const int len  = token_sizes[b];
    const float* emb = emissions + (size_t)b * TMAXR * NTAGS;

    // ---- E column j as 64 bf16x2 pairs over consecutive k ----
    bf16x2 Eh[NTAGS / 2];
#pragma unroll
    for (int i = 0; i < NTAGS / 2; ++i) {
        float e0 = exp2f(transitions[(2 * i + 0) * NTAGS + j] * LOG2E_F);
        float e1 = exp2f(transitions[(2 * i + 1) * NTAGS + j] * LOG2E_F);
        Eh[i] = __floats2bfloat162_rn(e0, e1);
    }

    // ---- init: alpha0 = head + em[0]; m0 = blockmax; q = exp(a0-m0) ----
    float a0 = head_t[j] + emb[j];
    float wm = a0;
#pragma unroll
    for (int o = 16; o > 0; o >>= 1)
        wm = fmaxf(wm, __shfl_xor_sync(0xffffffff, wm, o));
    if (lane == 0) redbuf[warp] = wm;
    __syncthreads();
    float m0 = fmaxf(fmaxf(redbuf[0], redbuf[1]), fmaxf(redbuf[2], redbuf[3]));
    __syncthreads();

    bf16 qh   = __float2bfloat16(ex2((a0 - m0) * LOG2E_F));
    int  Mint = 0;

    // ---- emission pipeline: d_c = exp(em[t]) one step early; raw em 3 ahead ----
    float em_a = emb[2 * NTAGS + j];
    float em_b = emb[3 * NTAGS + j];
    float d_c  = ex2(emb[1 * NTAGS + j] * LOG2E_F);

    // One forward step using smem buffer PH (statically addressed).
#define STEP(PH, T)                                                          \
    do {                                                                     \
        (PH)[j] = qh;                                                        \
        __syncthreads();                                                     \
        unsigned short q0b = *reinterpret_cast<const unsigned short*>(&(PH)[0]); \
        unsigned eh = ((unsigned)q0b >> 7) & 0xffu;                          \
        eh = (eh == 0u) ? 127u : eh;                                         \
        float scale = __uint_as_float((254u - eh) << 23);                    \
        Mint += (int)eh - 127;                                               \
        bf16 hds = __float2bfloat16(d_c * scale);                            \
        const uint4* pv = (const uint4*)(PH);                                \
        bf16x2 s0 = __floats2bfloat162_rn(0.f, 0.f);                         \
        bf16x2 s1 = s0, s2 = s0, s3 = s0;                                    \
        _Pragma("unroll")                                                    \
        for (int i = 0; i < NTAGS / 8; ++i) {                                \
            uint4 v = pv[i];                                                 \
            s0 = __hfma2(as_bf2(v.x), Eh[4 * i + 0], s0);                    \
            s1 = __hfma2(as_bf2(v.y), Eh[4 * i + 1], s1);                    \
            s2 = __hfma2(as_bf2(v.z), Eh[4 * i + 2], s2);                    \
            s3 = __hfma2(as_bf2(v.w), Eh[4 * i + 3], s3);                    \
        }                                                                    \
        int tn = min((T) + 3, TMAXR - 1);                                    \
        float em_f = __ldg(emb + (size_t)tn * NTAGS + j);                    \
        float d_n  = ex2(em_a * LOG2E_F);                                    \
        bf16x2 u0 = __hadd2(s0, s1);                                         \
        bf16x2 u1 = __hadd2(s2, s3);                                         \
        bf16x2 u2 = __hadd2(u0, u1);                                         \
        bf16 sh = __hadd(__low2bfloat16(u2), __high2bfloat16(u2));           \
        qh = __hmul(sh, hds);                                                \
        em_a = em_b; em_b = em_f; d_c = d_n;                                 \
    } while (0)

    int t = 1;
    for (; t + 1 < len; t += 2) {
        STEP(ph0, t);
        STEP(ph1, t + 1);
    }
    if (t < len) {
        STEP(ph0, t);
    }
#undef STEP

    // ---- terminate: out[b] = m0 + Mint*ln2 + ln(sum_j q_j * exp(last_j)) ----
    float v = __bfloat162float(qh) * ex2(last_t[j] * LOG2E_F);
#pragma unroll
    for (int o = 16; o > 0; o >>= 1)
        v += __shfl_xor_sync(0xffffffff, v, o);
    __syncthreads();                 // redbuf reuse
    if (lane == 0) redbuf[warp] = v;
    __syncthreads();
    if (j == 0) {
        float sv = (redbuf[0] + redbuf[1]) + (redbuf[2] + redbuf[3]);
        double r = (double)m0 + (double)Mint * 0.6931471805599453094
                 + log((double)sv);
        out[b] = (float)r;
    }
}

extern "C" void kernel_launch(void* const* d_in, const int* in_sizes, int n_in,
                              void* d_out, int out_size) {
    const float* emissions   = (const float*)d_in[0];  // [64,2048,1,128]
    const int*   token_sizes = (const int*)  d_in[1];  // [64]
    const float* transitions = (const float*)d_in[2];  // [1,1,128,128]
    const float* head_t      = (const float*)d_in[3];  // [1,1,128]
    const float* last_t      = (const float*)d_in[4];  // [1,1,128]
    float* out = (float*)d_out;                        // [64,1]

    crf_logZ_kernel<<<64, 128>>>(emissions, token_sizes, transitions,
                                 head_t, last_t, out);
}